// round 9
// baseline (speedup 1.0000x reference)
#include <cuda_runtime.h>
#include <cuda_bf16.h>
#include <cstdint>

#define F_DIM   512
#define F4      (F_DIM / 4)     // 128 float4 per row
#define NGROUPS 1024
#define OUTK    7
#define TPB     128             // one float4 column per thread, 4 warps
#define RPB     85              // rows per block -> grid ~1177 (~7.95/SM, 1 wave)

// Scratch: zero-initialized .bss; finalize kernel re-zeros it after reading,
// so every launch (and every graph replay) sees zeros on entry. [7 dots + cnt]
__device__ float g_acc[NGROUPS][8];

// ---------------------------------------------------------------------------
// Kernel B: perfectly balanced accumulate. Block owns rows [bid*RPB, +RPB).
// Finds group runs in its slice (batch sorted -> runs are contiguous,
// block-uniform), accumulates each run with an 8-deep streaming pipeline,
// dots with W, block-reduces, atomicAdds 7 floats + count into g_acc.
// ---------------------------------------------------------------------------
__global__ __launch_bounds__(TPB, 8)
void accum_kernel(const float4* __restrict__ x4,
                  const int*    __restrict__ bw,   // batch as 32-bit words
                  const float4* __restrict__ W4g,
                  int N)
{
    const int t    = threadIdx.x;       // 0..127 == float4 column
    const int warp = t >> 5, lane = t & 31;
    const int r0   = blockIdx.x * RPB;
    const int nRows = min(RPB, N - r0);
    if (nRows <= 0) return;

    __shared__ int   sgid[RPB];
    __shared__ int   smi[4];
    __shared__ float redw[4][OUTK];

    // dtype probe (batch sorted 0..1023, last element nonzero):
    // int64 storage => odd 32-bit words (high words) are zero. L2-hot.
    const bool is64 = (bw[N - 1] == 0) && (bw[N - 3] == 0) && (bw[N - 5] == 0);

    // load this slice's group ids
    if (t < nRows) {
        int g = is64 ? bw[2 * (r0 + t)] : bw[r0 + t];
        sgid[t] = min(max(g, 0), NGROUPS - 1);
    }
    __syncthreads();

    const int BIG = 0x7fffffff;

    int i = 0;
    while (i < nRows) {
        const int gid = sgid[i];

        // --- find run end j: min over threads of first mismatch > i
        int cand = (t < nRows && t > i && sgid[t] != gid) ? t : BIG;
        #pragma unroll
        for (int off = 16; off > 0; off >>= 1)
            cand = min(cand, __shfl_xor_sync(0xffffffff, cand, off));
        if (lane == 0) smi[warp] = cand;
        __syncthreads();
        const int j = min(min(min(smi[0], smi[1]), min(smi[2], smi[3])), nRows);
        __syncthreads();

        // --- accumulate rows [r0+i, r0+j), 8-deep streaming pipeline
        float4 a0 = make_float4(0.f, 0.f, 0.f, 0.f);
        float4 a1 = make_float4(0.f, 0.f, 0.f, 0.f);
        float4 a2 = make_float4(0.f, 0.f, 0.f, 0.f);
        float4 a3 = make_float4(0.f, 0.f, 0.f, 0.f);
        const float4* p = x4 + (size_t)(r0 + i) * F4 + t;
        int n = j - i;
        for (; n >= 8; n -= 8, p += 8 * F4) {
            float4 v0 = __ldcs(p + 0 * F4);
            float4 v1 = __ldcs(p + 1 * F4);
            float4 v2 = __ldcs(p + 2 * F4);
            float4 v3 = __ldcs(p + 3 * F4);
            float4 v4 = __ldcs(p + 4 * F4);
            float4 v5 = __ldcs(p + 5 * F4);
            float4 v6 = __ldcs(p + 6 * F4);
            float4 v7 = __ldcs(p + 7 * F4);
            a0.x += v0.x; a0.y += v0.y; a0.z += v0.z; a0.w += v0.w;
            a1.x += v1.x; a1.y += v1.y; a1.z += v1.z; a1.w += v1.w;
            a2.x += v2.x; a2.y += v2.y; a2.z += v2.z; a2.w += v2.w;
            a3.x += v3.x; a3.y += v3.y; a3.z += v3.z; a3.w += v3.w;
            a0.x += v4.x; a0.y += v4.y; a0.z += v4.z; a0.w += v4.w;
            a1.x += v5.x; a1.y += v5.y; a1.z += v5.z; a1.w += v5.w;
            a2.x += v6.x; a2.y += v6.y; a2.z += v6.z; a2.w += v6.w;
            a3.x += v7.x; a3.y += v7.y; a3.z += v7.z; a3.w += v7.w;
        }
        for (; n > 0; n--, p += F4) {
            float4 v = __ldcs(p);
            a0.x += v.x; a0.y += v.y; a0.z += v.z; a0.w += v.w;
        }
        a0.x += a1.x; a0.y += a1.y; a0.z += a1.z; a0.w += a1.w;
        a2.x += a3.x; a2.y += a3.y; a2.z += a3.z; a2.w += a3.w;
        a0.x += a2.x; a0.y += a2.y; a0.z += a2.z; a0.w += a2.w;

        // --- 7 partial dots against W (tiny, L2-resident)
        float pr[OUTK];
        #pragma unroll
        for (int k = 0; k < OUTK; k++) {
            float4 w = __ldg(&W4g[k * F4 + t]);
            pr[k] = a0.x * w.x + a0.y * w.y + a0.z * w.z + a0.w * w.w;
        }
        #pragma unroll
        for (int off = 16; off > 0; off >>= 1) {
            #pragma unroll
            for (int k = 0; k < OUTK; k++)
                pr[k] += __shfl_xor_sync(0xffffffff, pr[k], off);
        }
        if (lane == 0) {
            #pragma unroll
            for (int k = 0; k < OUTK; k++) redw[warp][k] = pr[k];
        }
        __syncthreads();
        if (t < OUTK)
            atomicAdd(&g_acc[gid][t],
                      redw[0][t] + redw[1][t] + redw[2][t] + redw[3][t]);
        if (t == OUTK)
            atomicAdd(&g_acc[gid][7], (float)(j - i));
        __syncthreads();

        i = j;
    }
}

// ---------------------------------------------------------------------------
// Kernel C: out[g][k] = g_acc[g][k] / max(cnt,1) + b[k]; then re-zero g_acc
// (restores the zero-on-entry invariant for the next replay).
// ---------------------------------------------------------------------------
__global__ __launch_bounds__(128)
void finalize_kernel(const float* __restrict__ b,
                     float* __restrict__ out)
{
    const int g = blockIdx.x * 128 + threadIdx.x;   // 0..1023
    if (g >= NGROUPS) return;
    float4 s0 = *(const float4*)&g_acc[g][0];
    float4 s1 = *(const float4*)&g_acc[g][4];
    float inv = 1.0f / fmaxf(s1.w, 1.0f);           // s1.w = count
    out[g * OUTK + 0] = s0.x * inv + b[0];
    out[g * OUTK + 1] = s0.y * inv + b[1];
    out[g * OUTK + 2] = s0.z * inv + b[2];
    out[g * OUTK + 3] = s0.w * inv + b[3];
    out[g * OUTK + 4] = s1.x * inv + b[4];
    out[g * OUTK + 5] = s1.y * inv + b[5];
    out[g * OUTK + 6] = s1.z * inv + b[6];
    float4 z = make_float4(0.f, 0.f, 0.f, 0.f);
    *(float4*)&g_acc[g][0] = z;
    *(float4*)&g_acc[g][4] = z;
}

// ---------------------------------------------------------------------------
// Inputs (metadata order):
//   d_in[0] = x          float32 [100000, 512]
//   d_in[1] = edge_index (unused)
//   d_in[2] = edge_attr  (unused)
//   d_in[3] = batch      int64-or-int32 [100000] (probed in-kernel)
//   d_in[4] = W          float32 [7, 512]
//   d_in[5] = b          float32 [7]
// Output: float32 [1024, 7]
// ---------------------------------------------------------------------------
extern "C" void kernel_launch(void* const* d_in, const int* in_sizes, int n_in,
                              void* d_out, int out_size)
{
    const float4* x4  = (const float4*)d_in[0];
    const int*    bw  = (const int*)d_in[3];
    const float4* W4g = (const float4*)d_in[4];
    const float*  b   = (const float*)d_in[5];
    float*        out = (float*)d_out;

    const int N = in_sizes[3];

    accum_kernel<<<(N + RPB - 1) / RPB, TPB>>>(x4, bw, W4g, N);
    finalize_kernel<<<(NGROUPS + 127) / 128, 128>>>(b, out);
}